// round 13
// baseline (speedup 1.0000x reference)
#include <cuda_runtime.h>
#include <cuda_fp16.h>
#include <cstdint>

#define HIDDEN 1024
#define SEQ    2048
#define BATCH  2
#define HEADS  16
#define HD     64
#define MTOT   (BATCH*SEQ)   // 4096

typedef __half fp16;

// Scale folded into Q projection: 1/sqrt(64) * log2(e)
#define SCALE_Q (0.125f * 1.4426950408889634f)

// ---------------- scratch (device globals) -----------------------------------
__device__ fp16 g_x  [MTOT*HIDDEN];
__device__ fp16 g_q  [MTOT*HIDDEN];
__device__ fp16 g_k  [MTOT*HIDDEN];
__device__ fp16 g_v  [MTOT*HIDDEN];
__device__ fp16 g_ao [MTOT*HIDDEN];
__device__ fp16 g_w  [4*HIDDEN*HIDDEN];   // W^T, [n][k], fp16

// ---------------- helpers ----------------------------------------------------
__device__ __forceinline__ uint32_t smem_u32(const void* p) {
    uint32_t a;
    asm("{ .reg .u64 t; cvta.to.shared.u64 t, %1; cvt.u32.u64 %0, t; }"
        : "=r"(a) : "l"(p));
    return a;
}
__device__ __forceinline__ void cpasync16(uint32_t dst, const void* src) {
    asm volatile("cp.async.cg.shared.global [%0], [%1], 16;"
                 :: "r"(dst), "l"(src));
}
#define CP_COMMIT() asm volatile("cp.async.commit_group;" ::: "memory")
#define CP_WAIT1()  asm volatile("cp.async.wait_group 1;"  ::: "memory")
#define CP_WAIT0()  asm volatile("cp.async.wait_group 0;"  ::: "memory")

__device__ __forceinline__ void mma_fp16(float* c, const uint32_t* a,
                                         const uint32_t* b) {
    asm volatile(
        "mma.sync.aligned.m16n8k16.row.col.f32.f16.f16.f32 "
        "{%0,%1,%2,%3}, {%4,%5,%6,%7}, {%8,%9}, {%0,%1,%2,%3};"
        : "+f"(c[0]), "+f"(c[1]), "+f"(c[2]), "+f"(c[3])
        : "r"(a[0]), "r"(a[1]), "r"(a[2]), "r"(a[3]), "r"(b[0]), "r"(b[1]));
}
__device__ __forceinline__ void ldsm4(uint32_t* r, uint32_t addr) {
    asm volatile("ldmatrix.sync.aligned.m8n8.x4.shared.b16 {%0,%1,%2,%3}, [%4];"
                 : "=r"(r[0]), "=r"(r[1]), "=r"(r[2]), "=r"(r[3]) : "r"(addr));
}
__device__ __forceinline__ void ldsm4t(uint32_t* r, uint32_t addr) {
    asm volatile("ldmatrix.sync.aligned.m8n8.x4.trans.shared.b16 {%0,%1,%2,%3}, [%4];"
                 : "=r"(r[0]), "=r"(r[1]), "=r"(r[2]), "=r"(r[3]) : "r"(addr));
}
__device__ __forceinline__ void ldsm2t(uint32_t* r, uint32_t addr) {
    asm volatile("ldmatrix.sync.aligned.m8n8.x2.trans.shared.b16 {%0,%1}, [%2];"
                 : "=r"(r[0]), "=r"(r[1]) : "r"(addr));
}
__device__ __forceinline__ float ex2(float x) {
    float y;
    asm("ex2.approx.ftz.f32 %0, %1;" : "=f"(y) : "f"(x));
    return y;
}
__device__ __forceinline__ uint32_t h2ex2(uint32_t x) {
    uint32_t y;
    asm("ex2.approx.f16x2 %0, %1;" : "=r"(y) : "r"(x));
    return y;
}
__device__ __forceinline__ uint32_t h2max(uint32_t a, uint32_t b) {
    uint32_t r;
    asm("max.f16x2 %0, %1, %2;" : "=r"(r) : "r"(a), "r"(b));
    return r;
}
__device__ __forceinline__ uint32_t h2sub(uint32_t a, uint32_t b) {
    uint32_t r;
    asm("sub.f16x2 %0, %1, %2;" : "=r"(r) : "r"(a), "r"(b));
    return r;
}
__device__ __forceinline__ uint32_t packh2(float a, float b) {
    __half2 t = __floats2half2_rn(a, b);   // .x = a (low half)
    return *(uint32_t*)&t;
}
__device__ __forceinline__ float h2lo(uint32_t x) {
    __half2 h; *(uint32_t*)&h = x; return __low2float(h);
}
__device__ __forceinline__ float h2hi(uint32_t x) {
    __half2 h; *(uint32_t*)&h = x; return __high2float(h);
}

// ---------------- prep: x -> fp16 --------------------------------------------
__global__ __launch_bounds__(256) void split_x_kernel(const float* __restrict__ src) {
    int i = (blockIdx.x * 256 + threadIdx.x) * 4;
    float4 v = *(const float4*)&src[i];
    uint2 o;
    o.x = packh2(v.x, v.y);
    o.y = packh2(v.z, v.w);
    *(uint2*)&g_x[i] = o;
}

// ---------------- transpose weights: W[K][N] -> Wt[N][K] fp16 ----------------
// Coalesced output: each thread writes 4 consecutive k as one 8B store.
__global__ __launch_bounds__(256) void wtrans_kernel(
    const float* __restrict__ W0, const float* __restrict__ W1,
    const float* __restrict__ W2, const float* __restrict__ W3)
{
    __shared__ float t[32][33];
    const float* W = (blockIdx.z == 0) ? W0 : (blockIdx.z == 1) ? W1
                   : (blockIdx.z == 2) ? W2 : W3;
    fp16* ow = g_w + (size_t)blockIdx.z * HIDDEN * HIDDEN;
    int n0 = blockIdx.x * 32, k0 = blockIdx.y * 32;
    int tid = threadIdx.x;
    int tx = tid & 31, ty = tid >> 5;          // 32 x 8
#pragma unroll
    for (int i = 0; i < 4; i++)
        t[ty + 8 * i][tx] = W[(size_t)(k0 + ty + 8 * i) * HIDDEN + n0 + tx];
    __syncthreads();
    int n  = tid >> 3;                          // 0..31
    int kq = tid & 7;                           // 0..7 -> k = 4*kq
    float a = t[4 * kq + 0][n], b = t[4 * kq + 1][n];
    float c = t[4 * kq + 2][n], d = t[4 * kq + 3][n];
    uint2 o;
    o.x = packh2(a, b);
    o.y = packh2(c, d);
    *(uint2*)&ow[(size_t)(n0 + n) * HIDDEN + k0 + 4 * kq] = o;
}

// ---------------- fp16 GEMM via mma.sync + ldmatrix (round-9 proven) ---------
// C = A @ W^T + bias. CTA 128x128, K-chunk 32, 256 threads, 80B row stride.
#define KCH    32
#define NCHK   (HIDDEN / KCH)   // 32
#define ARR_B  (128 * 80)            // 10240 bytes per array
#define STG_B  (2 * ARR_B)           // 20480 bytes
#define GSMEM  (2 * STG_B)           // 40960 bytes

__device__ __forceinline__ void g_load_stage(
    uint32_t sbase, const fp16* __restrict__ A,
    const fp16* __restrict__ B, int ko, int tid)
{
#pragma unroll
    for (int l = 0; l < 2; l++) {
        int fi  = tid + 256 * l;
        int row = fi >> 2;
        int w   = fi & 3;
        uint32_t so = sbase + (uint32_t)(row * 80 + w * 16);
        size_t   go = (size_t)row * HIDDEN + ko + w * 8;
        cpasync16(so + 0 * ARR_B, A + go);
        cpasync16(so + 1 * ARR_B, B + go);
    }
}

__device__ __forceinline__ void g_compute_ldsm(
    uint32_t sb, int m_w, int n_w, int lane, float acc[4][4][4])
{
    const int lrow8 = (lane & 7) + ((lane >> 3) & 1) * 8;
    const int lhi16 = lane >> 4;
    const int bcol  = (lane >> 3) * 16;

    uint32_t B[4][4];
#pragma unroll
    for (int ni = 0; ni < 4; ni++) {
        uint32_t a = sb + 1 * ARR_B +
                     (uint32_t)((n_w + ni * 8 + (lane & 7)) * 80 + bcol);
        ldsm4(B[ni], a);
    }

#pragma unroll
    for (int ks = 0; ks < 2; ks++) {
#pragma unroll
        for (int mi = 0; mi < 4; mi++) {
            uint32_t a = sb +
                (uint32_t)((m_w + mi * 16 + lrow8) * 80 + ks * 32 + lhi16 * 16);
            uint32_t ar[4];
            ldsm4(ar, a);
#pragma unroll
            for (int ni = 0; ni < 4; ni++)
                mma_fp16(acc[mi][ni], ar, B[ni] + 2 * ks);
        }
    }
}

__device__ __forceinline__ void gemm_body_mma(
    const fp16* __restrict__ A0, const fp16* __restrict__ B0,
    const float* __restrict__ bias,
    float* __restrict__ Cf, fp16* __restrict__ Ch,
    float scale, int m0, int n0)
{
    extern __shared__ char sm[];
    const int tid  = threadIdx.x;
    const int wid  = tid >> 5;
    const int lane = tid & 31;
    const int lr = lane >> 2, lc = lane & 3;
    const int m_w = (wid & 1) * 64;
    const int n_w = (wid >> 1) * 32;

    const fp16* A = A0 + (size_t)m0 * HIDDEN;
    const fp16* B = B0 + (size_t)n0 * HIDDEN;

    float acc[4][4][4];
#pragma unroll
    for (int i = 0; i < 4; i++)
#pragma unroll
        for (int j = 0; j < 4; j++)
#pragma unroll
            for (int k = 0; k < 4; k++) acc[i][j][k] = 0.0f;

    const uint32_t sb = smem_u32(sm);
    g_load_stage(sb, A, B, 0, tid);
    CP_COMMIT();

    for (int c = 0; c < NCHK; c++) {
        CP_WAIT0();
        __syncthreads();
        if (c + 1 < NCHK) {
            g_load_stage(sb + ((c + 1) & 1) * STG_B, A, B, (c + 1) * KCH, tid);
            CP_COMMIT();
        }
        g_compute_ldsm(sb + (c & 1) * STG_B, m_w, n_w, lane, acc);
    }

#pragma unroll
    for (int mi = 0; mi < 4; mi++) {
#pragma unroll
        for (int ni = 0; ni < 4; ni++) {
            int row = m0 + m_w + mi * 16 + lr;
            int col = n0 + n_w + ni * 8 + lc * 2;
            float b0 = bias[col], b1 = bias[col + 1];
            float v00 = (acc[mi][ni][0] + b0) * scale;
            float v01 = (acc[mi][ni][1] + b1) * scale;
            float v10 = (acc[mi][ni][2] + b0) * scale;
            float v11 = (acc[mi][ni][3] + b1) * scale;
            if (Cf) {
                *(float2*)&Cf[(size_t)row * HIDDEN + col]       = make_float2(v00, v01);
                *(float2*)&Cf[(size_t)(row + 8) * HIDDEN + col] = make_float2(v10, v11);
            } else {
                *(uint32_t*)&Ch[(size_t)row * HIDDEN + col]       = packh2(v00, v01);
                *(uint32_t*)&Ch[(size_t)(row + 8) * HIDDEN + col] = packh2(v10, v11);
            }
        }
    }
}

__global__ __launch_bounds__(256, 2) void gemm_qkv_kernel(
    const float* __restrict__ bq, const float* __restrict__ bk,
    const float* __restrict__ bv)
{
    const fp16* B; const float* bias; fp16* C; float scale;
    if (blockIdx.z == 0)      { B = g_w;                       bias = bq; C = g_q; scale = SCALE_Q; }
    else if (blockIdx.z == 1) { B = g_w + 1 * HIDDEN * HIDDEN; bias = bk; C = g_k; scale = 1.0f; }
    else                      { B = g_w + 2 * HIDDEN * HIDDEN; bias = bv; C = g_v; scale = 1.0f; }
    gemm_body_mma(g_x, B, bias, nullptr, C, scale,
                  blockIdx.y * 128, blockIdx.x * 128);
}

__global__ __launch_bounds__(256, 2) void gemm_o_kernel(
    const float* __restrict__ bo, float* __restrict__ out)
{
    gemm_body_mma(g_ao, g_w + 3 * HIDDEN * HIDDEN, bo, out, nullptr, 1.0f,
                  blockIdx.y * 128, blockIdx.x * 128);
}

// ---------------- flash attention, fp16 (r11 config + f16x2 softmax) ---------
// CTA: 256 threads (8 warps), q-tile 128 (warp = 16 rows), key tiles of 64.
// 3-stage KV pipeline; l carried as V-column 64 (ones); softmax in f16x2.
#define AT_RSB   144
#define AT_KTILE (64 * AT_RSB)                  // 9216
#define AT_STGB  (2 * AT_KTILE)                 // 18432 per stage (K + V)
#define AT_STG(s) ((s) * AT_STGB)
#define AT_QOFF  (3 * AT_STGB)
#define AT_SMEM  (3 * AT_STGB + 18432)          // 73728
#define NKT      (SEQ / 64)                     // 32

__device__ __forceinline__ void at_load_kv(uint32_t sdst, size_t gbase,
                                           int kt, int tid)
{
    int row = tid >> 2;               // 0..63
    int c0  = (tid & 3) * 32;         // bytes
    size_t go = gbase + (size_t)(kt + row) * HIDDEN;
    const char* kp = (const char*)(g_k + go);
    const char* vp = (const char*)(g_v + go);
    uint32_t sd = sdst + (uint32_t)(row * AT_RSB + c0);
#pragma unroll
    for (int i = 0; i < 2; i++) {
        cpasync16(sd + 0 * AT_KTILE + i * 16, kp + c0 + i * 16);
        cpasync16(sd + 1 * AT_KTILE + i * 16, vp + c0 + i * 16);
    }
}

__global__ __launch_bounds__(256, 2) void attn_mma_kernel()
{
    extern __shared__ char sma[];
    const int tid  = threadIdx.x;
    const int wid  = tid >> 5;
    const int lane = tid & 31;
    const int q0 = blockIdx.x * 128;
    const int h  = blockIdx.y;
    const int b  = blockIdx.z;
    const size_t base = (size_t)b * SEQ * HIDDEN + (size_t)h * HD;
    const uint32_t sb = smem_u32(sma);

    // Q (fp16) into its own staging area.
    {
        int row = tid >> 1;
        int c0  = (tid & 1) * 64;
        size_t go = base + (size_t)(q0 + row) * HIDDEN;
        const char* qp = (const char*)(g_q + go);
        uint32_t sd = sb + AT_QOFF + (uint32_t)(row * AT_RSB + c0);
#pragma unroll
        for (int i = 0; i < 4; i++)
            cpasync16(sd + i * 16, qp + c0 + i * 16);
    }
    CP_COMMIT();                                     // g0: Q
    at_load_kv(sb + AT_STG(0), base, 0, tid);
    CP_COMMIT();                                     // g1: KV0
    at_load_kv(sb + AT_STG(1), base, 64, tid);
    CP_COMMIT();                                     // g2: KV1

    // V padding cols 64..71 of all 3 stages: col64 = 1.0, rest 0.
    // Disjoint bytes (128..143) from cp.async writes (0..127); no race.
    if (tid < 192) {
        int st = tid >> 6;
        int r  = tid & 63;
        uint32_t addr = sb + AT_STG(st) + AT_KTILE + (uint32_t)(r * AT_RSB + 128);
        asm volatile("st.shared.v4.b32 [%0], {%1,%2,%3,%4};"
                     :: "r"(addr), "r"(0x3C00u), "r"(0u), "r"(0u), "r"(0u)
                     : "memory");
    }

    uint32_t qh[4][4];
    float    s[8][4], o[8][4], osum[4];
    float m0 = -1e30f, m1 = -1e30f;
#pragma unroll
    for (int i = 0; i < 8; i++)
#pragma unroll
        for (int j = 0; j < 4; j++) o[i][j] = 0.0f;
#pragma unroll
    for (int j = 0; j < 4; j++) osum[j] = 0.0f;

    const int lrow8 = (lane & 7) + ((lane >> 3) & 1) * 8;
    const int lhi16 = (lane >> 4);

    int sidx = 0;
    for (int t = 0; t < NKT; t++) {
        if (t + 1 < NKT) { CP_WAIT1(); } else { CP_WAIT0(); }
        __syncthreads();

        if (t == 0) {
#pragma unroll
            for (int j = 0; j < 4; j++) {
                uint32_t a = sb + AT_QOFF +
                    (uint32_t)((wid * 16 + lrow8) * AT_RSB + j * 32 + lhi16 * 16);
                ldsm4(qh[j], a);
            }
        }

        if (t + 2 < NKT) {
            int ps = sidx + 2; if (ps >= 3) ps -= 3;
            at_load_kv(sb + AT_STG(ps), base, (t + 2) * 64, tid);
            CP_COMMIT();
        }

        const uint32_t skh = sb + AT_STG(sidx);
        const uint32_t svh = skh + AT_KTILE;

        // ---- S = Q · K^T ----
#pragma unroll
        for (int nt = 0; nt < 8; nt++) {
#pragma unroll
            for (int j = 0; j < 4; j++) s[nt][j] = 0.0f;
#pragma unroll
            for (int g = 0; g < 2; g++) {
                uint32_t kb[4];
                uint32_t a = skh +
                    (uint32_t)((nt * 8 + (lane & 7)) * AT_RSB + g * 64 + (lane >> 3) * 16);
                ldsm4(kb, a);
                mma_fp16(s[nt], qh[2 * g],     kb);
                mma_fp16(s[nt], qh[2 * g + 1], kb + 2);
            }
        }

        // ---- online softmax in f16x2 (base-2; scale folded into Q) ----
        // Pack scores: u0[nt] = row r cols pair, u1[nt] = row r+8 pair.
        uint32_t u0[8], u1[8];
#pragma unroll
        for (int nt = 0; nt < 8; nt++) {
            u0[nt] = packh2(s[nt][0], s[nt][1]);
            u1[nt] = packh2(s[nt][2], s[nt][3]);
        }
        // Tree max (f16x2), then horizontal + cross-lane in f32.
        uint32_t A0 = h2max(h2max(h2max(u0[0], u0[1]), h2max(u0[2], u0[3])),
                            h2max(h2max(u0[4], u0[5]), h2max(u0[6], u0[7])));
        uint32_t A1 = h2max(h2max(h2max(u1[0], u1[1]), h2max(u1[2], u1[3])),
                            h2max(h2max(u1[4], u1[5]), h2max(u1[6], u1[7])));
        float tm0 = fmaxf(h2lo(A0), h2hi(A0));
        float tm1 = fmaxf(h2lo(A1), h2hi(A1));
        tm0 = fmaxf(tm0, __shfl_xor_sync(0xffffffffu, tm0, 1));
        tm0 = fmaxf(tm0, __shfl_xor_sync(0xffffffffu, tm0, 2));
        tm1 = fmaxf(tm1, __shfl_xor_sync(0xffffffffu, tm1, 1));
        tm1 = fmaxf(tm1, __shfl_xor_sync(0xffffffffu, tm1, 2));

        float mn0 = fmaxf(m0, tm0), mn1 = fmaxf(m1, tm1);
        float cr0 = ex2(m0 - mn0),  cr1 = ex2(m1 - mn1);
        m0 = mn0; m1 = mn1;

        uint32_t mh0 = packh2(mn0, mn0), mh1 = packh2(mn1, mn1);
        uint32_t ah[4][4];
#pragma unroll
        for (int nt = 0; nt < 8; nt++) {
            int kg = nt >> 1, hf = (nt & 1) * 2;
            ah[kg][hf + 0] = h2ex2(h2sub(u0[nt], mh0));
            ah[kg][hf + 1] = h2ex2(h2sub(u1[nt], mh1));
        }
        // Rescale o/l only when the running max actually moved (exact check).
        if (!__all_sync(0xffffffffu, (cr0 == 1.0f) && (cr1 == 1.0f))) {
#pragma unroll
            for (int nt = 0; nt < 8; nt++) {
                o[nt][0] *= cr0; o[nt][1] *= cr0;
                o[nt][2] *= cr1; o[nt][3] *= cr1;
            }
            osum[0] *= cr0; osum[1] *= cr0;
            osum[2] *= cr1; osum[3] *= cr1;
        }

        // ---- O += P · V, plus l via ones-column (col 64) ----
#pragma unroll
        for (int dp = 0; dp < 4; dp++) {
#pragma unroll
            for (int kg = 0; kg < 4; kg++) {
                uint32_t vb[4];
                uint32_t a = svh +
                    (uint32_t)((kg * 16 + lrow8) * AT_RSB + dp * 32 + lhi16 * 16);
                ldsm4t(vb, a);
                mma_fp16(o[2 * dp],     ah[kg], vb);
                mma_fp16(o[2 * dp + 1], ah[kg], vb + 2);
            }
        }
#pragma unroll
        for (int kg = 0; kg < 4; kg++) {
            uint32_t vs[2];
            uint32_t a = svh + (uint32_t)((kg * 16 + lrow8) * AT_RSB + 128);
            ldsm2t(vs, a);
            mma_fp16(osum, ah[kg], vs);
        }

        if (++sidx == 3) sidx = 0;
    }

    // ---- epilogue: extract l (col 64 in lc==0 lanes), normalize, store ----
    float l0 = __shfl_sync(0xffffffffu, osum[0], lane & 28);
    float l1 = __shfl_sync(0xffffffffu, osum[2], lane & 28);
    float inv0 = 1.0f / l0, inv1 = 1.0f / l1;
    int r0 = q0 + wid * 16 + (lane >> 2);
    int cbase = (lane & 3) * 2;
#pragma unroll
    for (int nt = 0; nt < 8; nt++) {
        int col = nt * 8 + cbase;
        size_t o0 = base + (size_t)r0 * HIDDEN + col;
        size_t o1 = base + (size_t)(r0 + 8) * HIDDEN + col;
        *(uint32_t*)&g_ao[o0] = packh2(o[nt][0] * inv0, o[nt][1] * inv0);
        *(uint32_t*)&g_ao[o1] = packh2(o[nt][2] * inv1, o[nt][3] * inv1);
    }
}

// ---------------------------------------------------------------------------
extern "C" void kernel_launch(void* const* d_in, const int* in_sizes, int n_in,
                              void* d_out, int out_size)
{
    const float* x  = (const float*)d_in[0];
    const float* Wq = (const float*)d_in[1];
    const float* bq = (const float*)d_in[2];
    const float* Wk = (const float*)d_in[3];
    const float* bk = (const float*)d_in[4];
    const float* Wv = (const float*)d_in[5];
    const float* bv = (const float*)d_in[6];
    const float* Wo = (const float*)d_in[7];
    const float* bo = (const float*)d_in[8];
    float* out = (float*)d_out;

    static int attr_set = 0;
    if (!attr_set) {
        cudaFuncSetAttribute(gemm_qkv_kernel,
                             cudaFuncAttributeMaxDynamicSharedMemorySize, GSMEM);
        cudaFuncSetAttribute(gemm_o_kernel,
                             cudaFuncAttributeMaxDynamicSharedMemorySize, GSMEM);
        cudaFuncSetAttribute(attn_mma_kernel,
                             cudaFuncAttributeMaxDynamicSharedMemorySize, AT_SMEM);
        attr_set = 1;
    }

    split_x_kernel<<<MTOT * HIDDEN / 1024, 256>>>(x);
    wtrans_kernel<<<dim3(32, 32, 4), 256>>>(Wq, Wk, Wv, Wo);
    gemm_qkv_kernel<<<dim3(HIDDEN / 128, MTOT / 128, 3), 256, GSMEM>>>(bq, bk, bv);
    attn_mma_kernel<<<dim3(SEQ / 128, HEADS, BATCH), 256, AT_SMEM>>>();
    gemm_o_kernel<<<dim3(HIDDEN / 128, MTOT / 128, 1), 256, GSMEM>>>(bo, out);
}

// round 15
// speedup vs baseline: 1.0152x; 1.0152x over previous
#include <cuda_runtime.h>
#include <cuda_fp16.h>
#include <cstdint>

#define HIDDEN 1024
#define SEQ    2048
#define BATCH  2
#define HEADS  16
#define HD     64
#define MTOT   (BATCH*SEQ)   // 4096

typedef __half fp16;

// Scale folded into Q projection: 1/sqrt(64) * log2(e)
#define SCALE_Q (0.125f * 1.4426950408889634f)

// ---------------- scratch (device globals) -----------------------------------
__device__ fp16 g_x  [MTOT*HIDDEN];
__device__ fp16 g_q  [MTOT*HIDDEN];
__device__ fp16 g_k  [MTOT*HIDDEN];
__device__ fp16 g_v  [MTOT*HIDDEN];
__device__ fp16 g_ao [MTOT*HIDDEN];
__device__ fp16 g_w  [4*HIDDEN*HIDDEN];   // W^T, [n][k], fp16

// ---------------- helpers ----------------------------------------------------
__device__ __forceinline__ uint32_t smem_u32(const void* p) {
    uint32_t a;
    asm("{ .reg .u64 t; cvta.to.shared.u64 t, %1; cvt.u32.u64 %0, t; }"
        : "=r"(a) : "l"(p));
    return a;
}
__device__ __forceinline__ void cpasync16(uint32_t dst, const void* src) {
    asm volatile("cp.async.cg.shared.global [%0], [%1], 16;"
                 :: "r"(dst), "l"(src));
}
#define CP_COMMIT() asm volatile("cp.async.commit_group;" ::: "memory")
#define CP_WAIT1()  asm volatile("cp.async.wait_group 1;"  ::: "memory")
#define CP_WAIT0()  asm volatile("cp.async.wait_group 0;"  ::: "memory")

__device__ __forceinline__ void mma_fp16(float* c, const uint32_t* a,
                                         const uint32_t* b) {
    asm volatile(
        "mma.sync.aligned.m16n8k16.row.col.f32.f16.f16.f32 "
        "{%0,%1,%2,%3}, {%4,%5,%6,%7}, {%8,%9}, {%0,%1,%2,%3};"
        : "+f"(c[0]), "+f"(c[1]), "+f"(c[2]), "+f"(c[3])
        : "r"(a[0]), "r"(a[1]), "r"(a[2]), "r"(a[3]), "r"(b[0]), "r"(b[1]));
}
__device__ __forceinline__ void ldsm4(uint32_t* r, uint32_t addr) {
    asm volatile("ldmatrix.sync.aligned.m8n8.x4.shared.b16 {%0,%1,%2,%3}, [%4];"
                 : "=r"(r[0]), "=r"(r[1]), "=r"(r[2]), "=r"(r[3]) : "r"(addr));
}
__device__ __forceinline__ void ldsm4t(uint32_t* r, uint32_t addr) {
    asm volatile("ldmatrix.sync.aligned.m8n8.x4.trans.shared.b16 {%0,%1,%2,%3}, [%4];"
                 : "=r"(r[0]), "=r"(r[1]), "=r"(r[2]), "=r"(r[3]) : "r"(addr));
}
__device__ __forceinline__ void ldsm2t(uint32_t* r, uint32_t addr) {
    asm volatile("ldmatrix.sync.aligned.m8n8.x2.trans.shared.b16 {%0,%1}, [%2];"
                 : "=r"(r[0]), "=r"(r[1]) : "r"(addr));
}
__device__ __forceinline__ float ex2(float x) {
    float y;
    asm("ex2.approx.ftz.f32 %0, %1;" : "=f"(y) : "f"(x));
    return y;
}
__device__ __forceinline__ uint32_t h2ex2(uint32_t x) {
    uint32_t y;
    asm("ex2.approx.f16x2 %0, %1;" : "=r"(y) : "r"(x));
    return y;
}
__device__ __forceinline__ uint32_t packh2(float a, float b) {
    __half2 t = __floats2half2_rn(a, b);   // .x = a (low half)
    return *(uint32_t*)&t;
}

// ---------------- prep: x -> fp16 --------------------------------------------
__global__ __launch_bounds__(256) void split_x_kernel(const float* __restrict__ src) {
    int i = (blockIdx.x * 256 + threadIdx.x) * 4;
    float4 v = *(const float4*)&src[i];
    uint2 o;
    o.x = packh2(v.x, v.y);
    o.y = packh2(v.z, v.w);
    *(uint2*)&g_x[i] = o;
}

// ---------------- transpose weights: W[K][N] -> Wt[N][K] fp16 ----------------
__global__ __launch_bounds__(256) void wtrans_kernel(
    const float* __restrict__ W0, const float* __restrict__ W1,
    const float* __restrict__ W2, const float* __restrict__ W3)
{
    __shared__ float t[32][33];
    const float* W = (blockIdx.z == 0) ? W0 : (blockIdx.z == 1) ? W1
                   : (blockIdx.z == 2) ? W2 : W3;
    fp16* ow = g_w + (size_t)blockIdx.z * HIDDEN * HIDDEN;
    int n0 = blockIdx.x * 32, k0 = blockIdx.y * 32;
    int tid = threadIdx.x;
    int tx = tid & 31, ty = tid >> 5;
#pragma unroll
    for (int i = 0; i < 4; i++)
        t[ty + 8 * i][tx] = W[(size_t)(k0 + ty + 8 * i) * HIDDEN + n0 + tx];
    __syncthreads();
    int n  = tid >> 3;
    int kq = tid & 7;
    float a = t[4 * kq + 0][n], b = t[4 * kq + 1][n];
    float c = t[4 * kq + 2][n], d = t[4 * kq + 3][n];
    uint2 o;
    o.x = packh2(a, b);
    o.y = packh2(c, d);
    *(uint2*)&ow[(size_t)(n0 + n) * HIDDEN + k0 + 4 * kq] = o;
}

// ---------------- fp16 GEMM via mma.sync + ldmatrix (round-9 proven) ---------
#define KCH    32
#define NCHK   (HIDDEN / KCH)   // 32
#define ARR_B  (128 * 80)
#define STG_B  (2 * ARR_B)
#define GSMEM  (2 * STG_B)

__device__ __forceinline__ void g_load_stage(
    uint32_t sbase, const fp16* __restrict__ A,
    const fp16* __restrict__ B, int ko, int tid)
{
#pragma unroll
    for (int l = 0; l < 2; l++) {
        int fi  = tid + 256 * l;
        int row = fi >> 2;
        int w   = fi & 3;
        uint32_t so = sbase + (uint32_t)(row * 80 + w * 16);
        size_t   go = (size_t)row * HIDDEN + ko + w * 8;
        cpasync16(so + 0 * ARR_B, A + go);
        cpasync16(so + 1 * ARR_B, B + go);
    }
}

__device__ __forceinline__ void g_compute_ldsm(
    uint32_t sb, int m_w, int n_w, int lane, float acc[4][4][4])
{
    const int lrow8 = (lane & 7) + ((lane >> 3) & 1) * 8;
    const int lhi16 = lane >> 4;
    const int bcol  = (lane >> 3) * 16;

    uint32_t B[4][4];
#pragma unroll
    for (int ni = 0; ni < 4; ni++) {
        uint32_t a = sb + 1 * ARR_B +
                     (uint32_t)((n_w + ni * 8 + (lane & 7)) * 80 + bcol);
        ldsm4(B[ni], a);
    }

#pragma unroll
    for (int ks = 0; ks < 2; ks++) {
#pragma unroll
        for (int mi = 0; mi < 4; mi++) {
            uint32_t a = sb +
                (uint32_t)((m_w + mi * 16 + lrow8) * 80 + ks * 32 + lhi16 * 16);
            uint32_t ar[4];
            ldsm4(ar, a);
#pragma unroll
            for (int ni = 0; ni < 4; ni++)
                mma_fp16(acc[mi][ni], ar, B[ni] + 2 * ks);
        }
    }
}

__device__ __forceinline__ void gemm_body_mma(
    const fp16* __restrict__ A0, const fp16* __restrict__ B0,
    const float* __restrict__ bias,
    float* __restrict__ Cf, fp16* __restrict__ Ch,
    float scale, int m0, int n0)
{
    extern __shared__ char sm[];
    const int tid  = threadIdx.x;
    const int wid  = tid >> 5;
    const int lane = tid & 31;
    const int lr = lane >> 2, lc = lane & 3;
    const int m_w = (wid & 1) * 64;
    const int n_w = (wid >> 1) * 32;

    const fp16* A = A0 + (size_t)m0 * HIDDEN;
    const fp16* B = B0 + (size_t)n0 * HIDDEN;

    float acc[4][4][4];
#pragma unroll
    for (int i = 0; i < 4; i++)
#pragma unroll
        for (int j = 0; j < 4; j++)
#pragma unroll
            for (int k = 0; k < 4; k++) acc[i][j][k] = 0.0f;

    const uint32_t sb = smem_u32(sm);
    g_load_stage(sb, A, B, 0, tid);
    CP_COMMIT();

    for (int c = 0; c < NCHK; c++) {
        CP_WAIT0();
        __syncthreads();
        if (c + 1 < NCHK) {
            g_load_stage(sb + ((c + 1) & 1) * STG_B, A, B, (c + 1) * KCH, tid);
            CP_COMMIT();
        }
        g_compute_ldsm(sb + (c & 1) * STG_B, m_w, n_w, lane, acc);
    }

#pragma unroll
    for (int mi = 0; mi < 4; mi++) {
#pragma unroll
        for (int ni = 0; ni < 4; ni++) {
            int row = m0 + m_w + mi * 16 + lr;
            int col = n0 + n_w + ni * 8 + lc * 2;
            float b0 = bias[col], b1 = bias[col + 1];
            float v00 = (acc[mi][ni][0] + b0) * scale;
            float v01 = (acc[mi][ni][1] + b1) * scale;
            float v10 = (acc[mi][ni][2] + b0) * scale;
            float v11 = (acc[mi][ni][3] + b1) * scale;
            if (Cf) {
                *(float2*)&Cf[(size_t)row * HIDDEN + col]       = make_float2(v00, v01);
                *(float2*)&Cf[(size_t)(row + 8) * HIDDEN + col] = make_float2(v10, v11);
            } else {
                *(uint32_t*)&Ch[(size_t)row * HIDDEN + col]       = packh2(v00, v01);
                *(uint32_t*)&Ch[(size_t)(row + 8) * HIDDEN + col] = packh2(v10, v11);
            }
        }
    }
}

__global__ __launch_bounds__(256, 2) void gemm_qkv_kernel(
    const float* __restrict__ bq, const float* __restrict__ bk,
    const float* __restrict__ bv)
{
    const fp16* B; const float* bias; fp16* C; float scale;
    if (blockIdx.z == 0)      { B = g_w;                       bias = bq; C = g_q; scale = SCALE_Q; }
    else if (blockIdx.z == 1) { B = g_w + 1 * HIDDEN * HIDDEN; bias = bk; C = g_k; scale = 1.0f; }
    else                      { B = g_w + 2 * HIDDEN * HIDDEN; bias = bv; C = g_v; scale = 1.0f; }
    gemm_body_mma(g_x, B, bias, nullptr, C, scale,
                  blockIdx.y * 128, blockIdx.x * 128);
}

__global__ __launch_bounds__(256, 2) void gemm_o_kernel(
    const float* __restrict__ bo, float* __restrict__ out)
{
    gemm_body_mma(g_ao, g_w + 3 * HIDDEN * HIDDEN, bo, out, nullptr, 1.0f,
                  blockIdx.y * 128, blockIdx.x * 128);
}

// ---------------- flash attention, fp16, PING-PONG mainloop ------------------
// CTA: 256 threads (8 warps), q-tile 128 (warp = 16 rows), key tiles of 64.
// 4-stage KV ring, prefetch distance 2, ONE barrier per tile.
// Tile order per iteration t: QK(t) MMAs -> PV(t-1) MMAs -> softmax(t).
// Softmax(t)'s inputs retire behind the PV burst; P(t) consumed next iter.
// l carried as V-column 64 (ones); final PV after the loop.
#define AT_RSB   144
#define AT_KTILE (64 * AT_RSB)                  // 9216
#define AT_STGB  (2 * AT_KTILE)                 // 18432 per stage (K + V)
#define AT_STG(s) ((s) * AT_STGB)
#define AT_QOFF  (4 * AT_STGB)                  // 73728
#define AT_SMEM  (4 * AT_STGB + 18432)          // 92160 -> 2 CTAs/SM
#define NKT      (SEQ / 64)                     // 32

__device__ __forceinline__ void at_load_kv(uint32_t sdst, size_t gbase,
                                           int kt, int tid)
{
    int row = tid >> 2;               // 0..63
    int c0  = (tid & 3) * 32;         // bytes
    size_t go = gbase + (size_t)(kt + row) * HIDDEN;
    const char* kp = (const char*)(g_k + go);
    const char* vp = (const char*)(g_v + go);
    uint32_t sd = sdst + (uint32_t)(row * AT_RSB + c0);
#pragma unroll
    for (int i = 0; i < 2; i++) {
        cpasync16(sd + 0 * AT_KTILE + i * 16, kp + c0 + i * 16);
        cpasync16(sd + 1 * AT_KTILE + i * 16, vp + c0 + i * 16);
    }
}

__global__ __launch_bounds__(256, 2) void attn_mma_kernel()
{
    extern __shared__ char sma[];
    const int tid  = threadIdx.x;
    const int wid  = tid >> 5;
    const int lane = tid & 31;
    const int q0 = blockIdx.x * 128;
    const int h  = blockIdx.y;
    const int b  = blockIdx.z;
    const size_t base = (size_t)b * SEQ * HIDDEN + (size_t)h * HD;
    const uint32_t sb = smem_u32(sma);

    // Q (fp16) into its own staging area.
    {
        int row = tid >> 1;
        int c0  = (tid & 1) * 64;
        size_t go = base + (size_t)(q0 + row) * HIDDEN;
        const char* qp = (const char*)(g_q + go);
        uint32_t sd = sb + AT_QOFF + (uint32_t)(row * AT_RSB + c0);
#pragma unroll
        for (int i = 0; i < 4; i++)
            cpasync16(sd + i * 16, qp + c0 + i * 16);
    }
    CP_COMMIT();                                     // g0: Q
    at_load_kv(sb + AT_STG(0), base, 0, tid);
    CP_COMMIT();                                     // g1: KV0
    at_load_kv(sb + AT_STG(1), base, 64, tid);
    CP_COMMIT();                                     // g2: KV1

    // V padding cols 64..71 of all 4 stages: col64 = 1.0, rest 0.
    // Disjoint bytes (128..143) from cp.async writes (0..127); no race.
    {
        int st = tid >> 6;            // 0..3
        int r  = tid & 63;
        uint32_t addr = sb + AT_STG(st) + AT_KTILE + (uint32_t)(r * AT_RSB + 128);
        asm volatile("st.shared.v4.b32 [%0], {%1,%2,%3,%4};"
                     :: "r"(addr), "r"(0x3C00u), "r"(0u), "r"(0u), "r"(0u)
                     : "memory");
    }

    uint32_t qh[4][4], ah[4][4];
    float    s[8][4], o[8][4], osum[4];
    float m0 = -1e30f, m1 = -1e30f;
#pragma unroll
    for (int i = 0; i < 8; i++)
#pragma unroll
        for (int j = 0; j < 4; j++) o[i][j] = 0.0f;
#pragma unroll
    for (int j = 0; j < 4; j++) osum[j] = 0.0f;

    const int lrow8 = (lane & 7) + ((lane >> 3) & 1) * 8;
    const int lhi16 = (lane >> 4);

    int sidx = 0;                                    // t % 4
    for (int t = 0; t < NKT; t++) {
        if (t + 1 < NKT) { CP_WAIT1(); } else { CP_WAIT0(); }
        __syncthreads();

        if (t == 0) {
#pragma unroll
            for (int j = 0; j < 4; j++) {
                uint32_t a = sb + AT_QOFF +
                    (uint32_t)((wid * 16 + lrow8) * AT_RSB + j * 32 + lhi16 * 16);
                ldsm4(qh[j], a);
            }
        }

        if (t + 2 < NKT) {
            at_load_kv(sb + AT_STG((sidx + 2) & 3), base, (t + 2) * 64, tid);
            CP_COMMIT();
        }

        const uint32_t skh = sb + AT_STG(sidx);

        // ---- QK(t): S = Q · K^T ----
#pragma unroll
        for (int nt = 0; nt < 8; nt++) {
#pragma unroll
            for (int j = 0; j < 4; j++) s[nt][j] = 0.0f;
#pragma unroll
            for (int g = 0; g < 2; g++) {
                uint32_t kb[4];
                uint32_t a = skh +
                    (uint32_t)((nt * 8 + (lane & 7)) * AT_RSB + g * 64 + (lane >> 3) * 16);
                ldsm4(kb, a);
                mma_fp16(s[nt], qh[2 * g],     kb);
                mma_fp16(s[nt], qh[2 * g + 1], kb + 2);
            }
        }

        // ---- PV(t-1): O += P(t-1) · V(t-1)  (covers QK(t) latency) ----
        if (t > 0) {
            const uint32_t pvh = sb + AT_STG((sidx + 3) & 3) + AT_KTILE;
#pragma unroll
            for (int dp = 0; dp < 4; dp++) {
#pragma unroll
                for (int kg = 0; kg < 4; kg++) {
                    uint32_t vb[4];
                    uint32_t a = pvh +
                        (uint32_t)((kg * 16 + lrow8) * AT_RSB + dp * 32 + lhi16 * 16);
                    ldsm4t(vb, a);
                    mma_fp16(o[2 * dp],     ah[kg], vb);
                    mma_fp16(o[2 * dp + 1], ah[kg], vb + 2);
                }
            }
#pragma unroll
            for (int kg = 0; kg < 4; kg++) {
                uint32_t vs[2];
                uint32_t a = pvh + (uint32_t)((kg * 16 + lrow8) * AT_RSB + 128);
                ldsm2t(vs, a);
                mma_fp16(osum, ah[kg], vs);
            }
        }

        // ---- softmax(t) -> ah (consumed next iteration) ----
        float tm0 = -1e30f, tm1 = -1e30f;
#pragma unroll
        for (int nt = 0; nt < 8; nt++) {
            tm0 = fmaxf(tm0, fmaxf(s[nt][0], s[nt][1]));
            tm1 = fmaxf(tm1, fmaxf(s[nt][2], s[nt][3]));
        }
        tm0 = fmaxf(tm0, __shfl_xor_sync(0xffffffffu, tm0, 1));
        tm0 = fmaxf(tm0, __shfl_xor_sync(0xffffffffu, tm0, 2));
        tm1 = fmaxf(tm1, __shfl_xor_sync(0xffffffffu, tm1, 1));
        tm1 = fmaxf(tm1, __shfl_xor_sync(0xffffffffu, tm1, 2));

        float mn0 = fmaxf(m0, tm0), mn1 = fmaxf(m1, tm1);
        float cr0 = ex2(m0 - mn0),  cr1 = ex2(m1 - mn1);
        m0 = mn0; m1 = mn1;

#pragma unroll
        for (int nt = 0; nt < 8; nt++) {
            int kg = nt >> 1, hf = (nt & 1) * 2;
            ah[kg][hf + 0] = h2ex2(packh2(s[nt][0] - mn0, s[nt][1] - mn0));
            ah[kg][hf + 1] = h2ex2(packh2(s[nt][2] - mn1, s[nt][3] - mn1));
        }
        // Rescale o/l only when the running max actually moved (exact check).
        if (!__all_sync(0xffffffffu, (cr0 == 1.0f) && (cr1 == 1.0f))) {
#pragma unroll
            for (int nt = 0; nt < 8; nt++) {
                o[nt][0] *= cr0; o[nt][1] *= cr0;
                o[nt][2] *= cr1; o[nt][3] *= cr1;
            }
            osum[0] *= cr0; osum[1] *= cr0;
            osum[2] *= cr1; osum[3] *= cr1;
        }

        sidx = (sidx + 1) & 3;
    }

    // ---- final PV(NKT-1) ----
    {
        const uint32_t pvh = sb + AT_STG((sidx + 3) & 3) + AT_KTILE;
#pragma unroll
        for (int dp = 0; dp < 4; dp++) {
#pragma unroll
            for (int kg = 0; kg < 4; kg++) {
                uint32_t vb[4];
                uint32_t a = pvh +
                    (uint32_t)((kg * 16 + lrow8) * AT_RSB + dp * 32 + lhi16 * 16);
                ldsm4t(vb, a);
                mma_fp16(o[2 * dp],     ah[kg], vb);
                mma_fp16(o[2 * dp + 1], ah[kg], vb + 2);
            }
        }
#pragma unroll
        for (int kg = 0; kg < 4; kg++) {
            uint32_t vs[2];
            uint32_t a = pvh + (uint32_t)((kg * 16 + lrow8) * AT_RSB + 128);
            ldsm2t(vs, a);
            mma_fp16(osum, ah[kg], vs);
        }
    }

    // ---- epilogue: extract l (col 64 in lc==0 lanes), normalize, store ----
    float l0 = __shfl_sync(0xffffffffu, osum[0], lane & 28);
    float l1 = __shfl_sync(0xffffffffu, osum[2], lane & 28);
    float inv0 = 1.0f / l0, inv1 = 1.0f / l1;
    int r0 = q0 + wid * 16 + (lane >> 2);
    int cbase = (lane & 3) * 2;
#pragma unroll
    for (int nt = 0; nt < 8; nt++) {
        int col = nt * 8 + cbase;
        size_t o0 = base + (size_t)r0 * HIDDEN + col;
        size_t o1 = base + (size_t)(r0 + 8) * HIDDEN + col;
        *(uint32_t*)&g_ao[o0] = packh2(o[nt][0] * inv0, o[nt][1] * inv0);
        *(uint32_t*)&g_ao[o1] = packh2(o[nt][2] * inv1, o[nt][3] * inv1);
    }
}

// ---------------------------------------------------------------------------
extern "C" void kernel_launch(void* const* d_in, const int* in_sizes, int n_in,
                              void* d_out, int out_size)
{
    const float* x  = (const float*)d_in[0];
    const float* Wq = (const float*)d_in[1];
    const float* bq = (const float*)d_in[2];
    const float* Wk = (const float*)d_in[3];
    const float* bk = (const float*)d_in[4];
    const float* Wv = (const float*)d_in[5];
    const float* bv = (const float*)d_in[6];
    const float* Wo = (const float*)d_in[7];
    const float* bo = (const float*)d_in[8];
    float* out = (float*)d_out;

    static int attr_set = 0;
    if (!attr_set) {
        cudaFuncSetAttribute(gemm_qkv_kernel,
                             cudaFuncAttributeMaxDynamicSharedMemorySize, GSMEM);
        cudaFuncSetAttribute(gemm_o_kernel,
                             cudaFuncAttributeMaxDynamicSharedMemorySize, GSMEM);
        cudaFuncSetAttribute(attn_mma_kernel,
                             cudaFuncAttributeMaxDynamicSharedMemorySize, AT_SMEM);
        attr_set = 1;
    }

    split_x_kernel<<<MTOT * HIDDEN / 1024, 256>>>(x);
    wtrans_kernel<<<dim3(32, 32, 4), 256>>>(Wq, Wk, Wv, Wo);
    gemm_qkv_kernel<<<dim3(HIDDEN / 128, MTOT / 128, 3), 256, GSMEM>>>(bq, bk, bv);
    attn_mma_kernel<<<dim3(SEQ / 128, HEADS, BATCH), 256, AT_SMEM>>>();
    gemm_o_kernel<<<dim3(HIDDEN / 128, MTOT / 128, 1), 256, GSMEM>>>(bo, out);
}